// round 11
// baseline (speedup 1.0000x reference)
#include <cuda_runtime.h>
#include <cuda_bf16.h>

#define NN    1500
#define NEDGE 24000
#define EDIM  64
#define LOOPN 10
#define EB2   375            // NEDGE/64 edge tiles (64 edges per block)
#define NT2   24             // ceil(NN/64) node tiles (64 nodes per block)

// ---------------- device scratch (static, allocation-free) ----------------
__device__ float g_vc[NN * 8];
__device__ float g_goal[8];
__device__ float g_x[NN * EDIM];
__device__ float g_y[NEDGE * EDIM];
__device__ float g_msg[NEDGE * EDIM];
__device__ float g_Pf[NN * EDIM], g_Qf[NN * EDIM];
__device__ float g_Py[NN * EDIM], g_Qy[NN * EDIM];
__device__ float g_A1[EDIM * EDIM], g_B1[EDIM * EDIM];
__device__ float g_A2[EDIM * EDIM], g_B2[EDIM * EDIM];
__device__ float g_Ay[8 * EDIM],   g_By[8 * EDIM];
__device__ int   g_rowptr[NN + 1];
__device__ int   g_cols[NEDGE];
__device__ int   g_winner[NN * NN];

#define NEG_INF __int_as_float(0xff800000)

#define FMA8(acc, v, w0, w1)                                   \
    {   acc[0] += (v) * (w0).x; acc[1] += (v) * (w0).y;        \
        acc[2] += (v) * (w0).z; acc[3] += (v) * (w0).w;        \
        acc[4] += (v) * (w1).x; acc[5] += (v) * (w1).y;        \
        acc[6] += (v) * (w1).z; acc[7] += (v) * (w1).w; }

// dynamic smem (floats): ONE weight buffer + ONE activations buffer
#define SM_FLOATS (4096 + 4160)     // 33 KB -> 6 CTAs/SM

// ---------------- prelude ----------------

__global__ void k_prep(const float* __restrict__ v, const float* __restrict__ labels,
                       const float* __restrict__ fxW1, const float* __restrict__ fyW1,
                       const float* __restrict__ hyW1) {
    __shared__ float bv[256];
    __shared__ int   bi[256];
    int t = threadIdx.x;
    for (int i = t; i < NN; i += 256) {
        #pragma unroll
        for (int j = 0; j < 7; j++) g_vc[i * 8 + j] = v[i * 7 + j];
        g_vc[i * 8 + 7] = labels[i];
    }
    float best = -1e30f; int idx = 0;
    for (int i = t; i < NN; i += 256) {
        float l = labels[i];
        if (l > best) { best = l; idx = i; }
    }
    bv[t] = best; bi[t] = idx;
    __syncthreads();
    for (int s = 128; s > 0; s >>= 1) {
        if (t < s) {
            if (bv[t + s] > bv[t] || (bv[t + s] == bv[t] && bi[t + s] < bi[t])) {
                bv[t] = bv[t + s]; bi[t] = bi[t + s];
            }
        }
        __syncthreads();
    }
    if (t < 8) g_goal[t] = g_vc[bi[0] * 8 + t];
    for (int i = t; i < 4096; i += 256) {
        g_A1[i] = fxW1[i] + fxW1[4096 + i];
        g_B1[i] = fxW1[8192 + i] - fxW1[i];
        g_A2[i] = fyW1[i] + fyW1[4096 + i];
        g_B2[i] = fyW1[8192 + i] - fyW1[i];
        if (i < 512) {
            g_Ay[i] = hyW1[i] + hyW1[512 + i];
            g_By[i] = hyW1[1024 + i] - hyW1[i];
        }
    }
}

__global__ void k_init(const float* __restrict__ W1, const float* __restrict__ b1,
                       const float* __restrict__ W2, const float* __restrict__ b2) {
    int i = blockIdx.x;
    int c = threadIdx.x;                 // 64 threads
    __shared__ float z[32], h[64];
    if (c < 8) {
        float vcv = g_vc[i * 8 + c];
        float gl  = g_goal[c];
        float d   = vcv - gl;
        z[c] = vcv; z[8 + c] = gl; z[16 + c] = d; z[24 + c] = d * d;
    }
    __syncthreads();
    float acc = b1[c];
    #pragma unroll
    for (int k = 0; k < 32; k++) acc += z[k] * W1[k * 64 + c];
    h[c] = fmaxf(acc, 0.0f);
    __syncthreads();
    float o = b2[c];
    #pragma unroll 16
    for (int k = 0; k < 64; k++) o += h[k] * W2[k * 64 + c];
    g_x[i * 64 + c] = o;
    float r = 0.f, s = 0.f;
    #pragma unroll
    for (int k = 0; k < 8; k++) {
        r += z[k] * g_Ay[k * 64 + c];
        s += z[k] * g_By[k * 64 + c];
    }
    g_Py[i * 64 + c] = r;
    g_Qy[i * 64 + c] = s;
}

// ---------------- fx edge kernel: 64 edges/block, 2 edges/thread ----------------
// smem: Ws (4096, holds Wy then W2), buf (4160, holds ys then hs)
__global__ void __launch_bounds__(256)
k_fx_edge(const float* __restrict__ Wy, const float* __restrict__ b1,
          const float* __restrict__ W2, const float* __restrict__ b2,
          const int* __restrict__ src, const int* __restrict__ tgt) {
    extern __shared__ float sm[];
    float* Ws  = sm;
    float* buf = sm + 4096;
    int tid = threadIdx.x;
    int e0  = blockIdx.x * 64;
    for (int idx = tid; idx < 4096; idx += 256) Ws[idx] = Wy[idx];
    for (int idx = tid; idx < 4096; idx += 256) {
        int el2 = idx >> 6, k = idx & 63;
        buf[k * 65 + el2] = g_y[(e0 + el2) * 64 + k];
    }
    __syncthreads();
    int el = tid >> 3, cg = tid & 7, c0 = cg * 8;
    int eA = e0 + el, eB = e0 + el + 32;
    float accA[8], accB[8];
    #pragma unroll
    for (int j = 0; j < 8; j++) { accA[j] = 0.f; accB[j] = 0.f; }
    #pragma unroll 4
    for (int k = 0; k < 64; k++) {
        float yA = buf[k * 65 + el];
        float yB = buf[k * 65 + el + 32];
        float4 w0 = *(const float4*)&Ws[k * 64 + c0];
        float4 w1 = *(const float4*)&Ws[k * 64 + c0 + 4];
        FMA8(accA, yA, w0, w1);
        FMA8(accB, yB, w0, w1);
    }
    float hA[8], hB[8];
    {
        int sA = src[eA], tA = tgt[eA];
        int sB = src[eB], tB = tgt[eB];
        float4 pA0 = *(const float4*)&g_Pf[sA * 64 + c0];
        float4 pA1 = *(const float4*)&g_Pf[sA * 64 + c0 + 4];
        float4 qA0 = *(const float4*)&g_Qf[tA * 64 + c0];
        float4 qA1 = *(const float4*)&g_Qf[tA * 64 + c0 + 4];
        float4 pB0 = *(const float4*)&g_Pf[sB * 64 + c0];
        float4 pB1 = *(const float4*)&g_Pf[sB * 64 + c0 + 4];
        float4 qB0 = *(const float4*)&g_Qf[tB * 64 + c0];
        float4 qB1 = *(const float4*)&g_Qf[tB * 64 + c0 + 4];
        hA[0] = fmaxf(accA[0] + pA0.x + qA0.x + b1[c0 + 0], 0.f);
        hA[1] = fmaxf(accA[1] + pA0.y + qA0.y + b1[c0 + 1], 0.f);
        hA[2] = fmaxf(accA[2] + pA0.z + qA0.z + b1[c0 + 2], 0.f);
        hA[3] = fmaxf(accA[3] + pA0.w + qA0.w + b1[c0 + 3], 0.f);
        hA[4] = fmaxf(accA[4] + pA1.x + qA1.x + b1[c0 + 4], 0.f);
        hA[5] = fmaxf(accA[5] + pA1.y + qA1.y + b1[c0 + 5], 0.f);
        hA[6] = fmaxf(accA[6] + pA1.z + qA1.z + b1[c0 + 6], 0.f);
        hA[7] = fmaxf(accA[7] + pA1.w + qA1.w + b1[c0 + 7], 0.f);
        hB[0] = fmaxf(accB[0] + pB0.x + qB0.x + b1[c0 + 0], 0.f);
        hB[1] = fmaxf(accB[1] + pB0.y + qB0.y + b1[c0 + 1], 0.f);
        hB[2] = fmaxf(accB[2] + pB0.z + qB0.z + b1[c0 + 2], 0.f);
        hB[3] = fmaxf(accB[3] + pB0.w + qB0.w + b1[c0 + 3], 0.f);
        hB[4] = fmaxf(accB[4] + pB1.x + qB1.x + b1[c0 + 4], 0.f);
        hB[5] = fmaxf(accB[5] + pB1.y + qB1.y + b1[c0 + 5], 0.f);
        hB[6] = fmaxf(accB[6] + pB1.z + qB1.z + b1[c0 + 6], 0.f);
        hB[7] = fmaxf(accB[7] + pB1.w + qB1.w + b1[c0 + 7], 0.f);
    }
    __syncthreads();   // all reads of buf (ys) and Ws (Wy) done
    // write hs into buf; reload W2 into Ws
    #pragma unroll
    for (int j = 0; j < 8; j++) {
        buf[(c0 + j) * 65 + el]      = hA[j];
        buf[(c0 + j) * 65 + el + 32] = hB[j];
    }
    for (int idx = tid; idx < 4096; idx += 256) Ws[idx] = W2[idx];
    __syncthreads();
    #pragma unroll
    for (int j = 0; j < 8; j++) { accA[j] = b2[c0 + j]; accB[j] = b2[c0 + j]; }
    #pragma unroll 4
    for (int k = 0; k < 64; k++) {
        float xA = buf[k * 65 + el];
        float xB = buf[k * 65 + el + 32];
        float4 w0 = *(const float4*)&Ws[k * 64 + c0];
        float4 w1 = *(const float4*)&Ws[k * 64 + c0 + 4];
        FMA8(accA, xA, w0, w1);
        FMA8(accB, xB, w0, w1);
    }
    *(float4*)&g_msg[eA * 64 + c0]     = make_float4(accA[0], accA[1], accA[2], accA[3]);
    *(float4*)&g_msg[eA * 64 + c0 + 4] = make_float4(accA[4], accA[5], accA[6], accA[7]);
    *(float4*)&g_msg[eB * 64 + c0]     = make_float4(accB[0], accB[1], accB[2], accB[3]);
    *(float4*)&g_msg[eB * 64 + c0 + 4] = make_float4(accB[4], accB[5], accB[6], accB[7]);
}

// ---------------- fused edge-y + node_A: 2 outputs/thread, 33 KB smem ----------------
template <int MODE>
__global__ void __launch_bounds__(256)
k_eyA(const float* __restrict__ b1, const float* __restrict__ W2,
      const float* __restrict__ b2,
      const int* __restrict__ src, const int* __restrict__ tgt) {
    extern __shared__ float sm[];
    float* Ws  = sm;
    float* buf = sm + 4096;
    int tid = threadIdx.x;
    int el = tid >> 3, cg = tid & 7, c0 = cg * 8;

    if (blockIdx.x < EB2) {
        // ---- edge y-MLP (64 edges) ----
        int e0 = blockIdx.x * 64;
        for (int idx = tid; idx < 4096; idx += 256) Ws[idx] = W2[idx];
        int eA = e0 + el, eB = e0 + el + 32;
        {
            int sA = src[eA], tA = tgt[eA];
            int sB = src[eB], tB = tgt[eB];
            float4 pA0 = *(const float4*)&g_Py[tA * 64 + c0];
            float4 pA1 = *(const float4*)&g_Py[tA * 64 + c0 + 4];
            float4 qA0 = *(const float4*)&g_Qy[sA * 64 + c0];
            float4 qA1 = *(const float4*)&g_Qy[sA * 64 + c0 + 4];
            float4 pB0 = *(const float4*)&g_Py[tB * 64 + c0];
            float4 pB1 = *(const float4*)&g_Py[tB * 64 + c0 + 4];
            float4 qB0 = *(const float4*)&g_Qy[sB * 64 + c0];
            float4 qB1 = *(const float4*)&g_Qy[sB * 64 + c0 + 4];
            buf[(c0 + 0) * 65 + el] = fmaxf(pA0.x + qA0.x + b1[c0 + 0], 0.f);
            buf[(c0 + 1) * 65 + el] = fmaxf(pA0.y + qA0.y + b1[c0 + 1], 0.f);
            buf[(c0 + 2) * 65 + el] = fmaxf(pA0.z + qA0.z + b1[c0 + 2], 0.f);
            buf[(c0 + 3) * 65 + el] = fmaxf(pA0.w + qA0.w + b1[c0 + 3], 0.f);
            buf[(c0 + 4) * 65 + el] = fmaxf(pA1.x + qA1.x + b1[c0 + 4], 0.f);
            buf[(c0 + 5) * 65 + el] = fmaxf(pA1.y + qA1.y + b1[c0 + 5], 0.f);
            buf[(c0 + 6) * 65 + el] = fmaxf(pA1.z + qA1.z + b1[c0 + 6], 0.f);
            buf[(c0 + 7) * 65 + el] = fmaxf(pA1.w + qA1.w + b1[c0 + 7], 0.f);
            buf[(c0 + 0) * 65 + el + 32] = fmaxf(pB0.x + qB0.x + b1[c0 + 0], 0.f);
            buf[(c0 + 1) * 65 + el + 32] = fmaxf(pB0.y + qB0.y + b1[c0 + 1], 0.f);
            buf[(c0 + 2) * 65 + el + 32] = fmaxf(pB0.z + qB0.z + b1[c0 + 2], 0.f);
            buf[(c0 + 3) * 65 + el + 32] = fmaxf(pB0.w + qB0.w + b1[c0 + 3], 0.f);
            buf[(c0 + 4) * 65 + el + 32] = fmaxf(pB1.x + qB1.x + b1[c0 + 4], 0.f);
            buf[(c0 + 5) * 65 + el + 32] = fmaxf(pB1.y + qB1.y + b1[c0 + 5], 0.f);
            buf[(c0 + 6) * 65 + el + 32] = fmaxf(pB1.z + qB1.z + b1[c0 + 6], 0.f);
            buf[(c0 + 7) * 65 + el + 32] = fmaxf(pB1.w + qB1.w + b1[c0 + 7], 0.f);
        }
        __syncthreads();
        float accA[8], accB[8];
        #pragma unroll
        for (int j = 0; j < 8; j++) { accA[j] = b2[c0 + j]; accB[j] = b2[c0 + j]; }
        #pragma unroll 4
        for (int k = 0; k < 64; k++) {
            float hA = buf[k * 65 + el];
            float hB = buf[k * 65 + el + 32];
            float4 w0 = *(const float4*)&Ws[k * 64 + c0];
            float4 w1 = *(const float4*)&Ws[k * 64 + c0 + 4];
            FMA8(accA, hA, w0, w1);
            FMA8(accB, hB, w0, w1);
        }
        if (MODE == 0) {
            *(float4*)&g_y[eA * 64 + c0]     = make_float4(accA[0], accA[1], accA[2], accA[3]);
            *(float4*)&g_y[eA * 64 + c0 + 4] = make_float4(accA[4], accA[5], accA[6], accA[7]);
            *(float4*)&g_y[eB * 64 + c0]     = make_float4(accB[0], accB[1], accB[2], accB[3]);
            *(float4*)&g_y[eB * 64 + c0 + 4] = make_float4(accB[4], accB[5], accB[6], accB[7]);
        } else {
            float4 ya0 = *(const float4*)&g_y[eA * 64 + c0];
            float4 ya1 = *(const float4*)&g_y[eA * 64 + c0 + 4];
            float4 yb0 = *(const float4*)&g_y[eB * 64 + c0];
            float4 yb1 = *(const float4*)&g_y[eB * 64 + c0 + 4];
            *(float4*)&g_y[eA * 64 + c0] = make_float4(
                fmaxf(ya0.x, accA[0]), fmaxf(ya0.y, accA[1]),
                fmaxf(ya0.z, accA[2]), fmaxf(ya0.w, accA[3]));
            *(float4*)&g_y[eA * 64 + c0 + 4] = make_float4(
                fmaxf(ya1.x, accA[4]), fmaxf(ya1.y, accA[5]),
                fmaxf(ya1.z, accA[6]), fmaxf(ya1.w, accA[7]));
            *(float4*)&g_y[eB * 64 + c0] = make_float4(
                fmaxf(yb0.x, accB[0]), fmaxf(yb0.y, accB[1]),
                fmaxf(yb0.z, accB[2]), fmaxf(yb0.w, accB[3]));
            *(float4*)&g_y[eB * 64 + c0 + 4] = make_float4(
                fmaxf(yb1.x, accB[4]), fmaxf(yb1.y, accB[5]),
                fmaxf(yb1.z, accB[6]), fmaxf(yb1.w, accB[7]));
        }
    } else {
        // ---- node_A: Pf = x@A1 then Qf = x@B1 (weight reload) ----
        int i0 = (blockIdx.x - EB2) * 64;
        for (int idx = tid; idx < 4096; idx += 256) Ws[idx] = g_A1[idx];
        for (int idx = tid; idx < 4096; idx += 256) {
            int nl2 = idx >> 6, k = idx & 63, i = i0 + nl2;
            buf[k * 65 + nl2] = (i < NN) ? g_x[i * 64 + k] : 0.f;
        }
        __syncthreads();
        int iA = i0 + el, iB = i0 + el + 32;
        float apA[8], apB[8];
        #pragma unroll
        for (int j = 0; j < 8; j++) { apA[j] = 0.f; apB[j] = 0.f; }
        #pragma unroll 4
        for (int k = 0; k < 64; k++) {
            float xA = buf[k * 65 + el];
            float xB = buf[k * 65 + el + 32];
            float4 a0 = *(const float4*)&Ws[k * 64 + c0];
            float4 a1 = *(const float4*)&Ws[k * 64 + c0 + 4];
            FMA8(apA, xA, a0, a1);
            FMA8(apB, xB, a0, a1);
        }
        if (iA < NN) {
            *(float4*)&g_Pf[iA * 64 + c0]     = make_float4(apA[0], apA[1], apA[2], apA[3]);
            *(float4*)&g_Pf[iA * 64 + c0 + 4] = make_float4(apA[4], apA[5], apA[6], apA[7]);
        }
        if (iB < NN) {
            *(float4*)&g_Pf[iB * 64 + c0]     = make_float4(apB[0], apB[1], apB[2], apB[3]);
            *(float4*)&g_Pf[iB * 64 + c0 + 4] = make_float4(apB[4], apB[5], apB[6], apB[7]);
        }
        __syncthreads();
        for (int idx = tid; idx < 4096; idx += 256) Ws[idx] = g_B1[idx];
        __syncthreads();
        #pragma unroll
        for (int j = 0; j < 8; j++) { apA[j] = 0.f; apB[j] = 0.f; }
        #pragma unroll 4
        for (int k = 0; k < 64; k++) {
            float xA = buf[k * 65 + el];
            float xB = buf[k * 65 + el + 32];
            float4 a0 = *(const float4*)&Ws[k * 64 + c0];
            float4 a1 = *(const float4*)&Ws[k * 64 + c0 + 4];
            FMA8(apA, xA, a0, a1);
            FMA8(apB, xB, a0, a1);
        }
        if (iA < NN) {
            *(float4*)&g_Qf[iA * 64 + c0]     = make_float4(apA[0], apA[1], apA[2], apA[3]);
            *(float4*)&g_Qf[iA * 64 + c0 + 4] = make_float4(apA[4], apA[5], apA[6], apA[7]);
        }
        if (iB < NN) {
            *(float4*)&g_Qf[iB * 64 + c0]     = make_float4(apB[0], apB[1], apB[2], apB[3]);
            *(float4*)&g_Qf[iB * 64 + c0 + 4] = make_float4(apB[4], apB[5], apB[6], apB[7]);
        }
    }
}

// ---------------- node_B: CSR gather-max + x update + A2/B2 GEMMs (reload) ----------------
__global__ void __launch_bounds__(256)
k_node_B() {
    extern __shared__ float sm[];
    float* Ws  = sm;
    float* buf = sm + 4096;   // xs
    int tid = threadIdx.x;
    int i0  = blockIdx.x * 64;
    for (int idx = tid; idx < 4096; idx += 256) Ws[idx] = g_A2[idx];
    int el = tid >> 3, cg = tid & 7, c0 = cg * 8;

    #pragma unroll
    for (int half = 0; half < 2; half++) {
        int nl = el + half * 32;
        int i = i0 + nl;
        if (i < NN) {
            float m[8];
            #pragma unroll
            for (int j = 0; j < 8; j++) m[j] = NEG_INF;
            int p0 = g_rowptr[i], p1 = g_rowptr[i + 1];
            for (int p = p0; p < p1; p++) {
                int e = g_cols[p];
                float4 a = *(const float4*)&g_msg[e * 64 + c0];
                float4 b = *(const float4*)&g_msg[e * 64 + c0 + 4];
                m[0] = fmaxf(m[0], a.x); m[1] = fmaxf(m[1], a.y);
                m[2] = fmaxf(m[2], a.z); m[3] = fmaxf(m[3], a.w);
                m[4] = fmaxf(m[4], b.x); m[5] = fmaxf(m[5], b.y);
                m[6] = fmaxf(m[6], b.z); m[7] = fmaxf(m[7], b.w);
            }
            if (p1 == p0) {
                #pragma unroll
                for (int j = 0; j < 8; j++) m[j] = 0.f;
            }
            #pragma unroll
            for (int j = 0; j < 8; j++) {
                float xn = fmaxf(g_x[i * 64 + c0 + j], m[j]);
                g_x[i * 64 + c0 + j] = xn;
                buf[(c0 + j) * 65 + nl] = xn;
            }
        } else {
            #pragma unroll
            for (int j = 0; j < 8; j++) buf[(c0 + j) * 65 + nl] = 0.f;
        }
    }
    __syncthreads();
    int iA = i0 + el, iB = i0 + el + 32;
    float apA[8], apB[8];
    #pragma unroll
    for (int j = 0; j < 8; j++) { apA[j] = 0.f; apB[j] = 0.f; }
    #pragma unroll 4
    for (int k = 0; k < 64; k++) {
        float xA = buf[k * 65 + el];
        float xB = buf[k * 65 + el + 32];
        float4 a0 = *(const float4*)&Ws[k * 64 + c0];
        float4 a1 = *(const float4*)&Ws[k * 64 + c0 + 4];
        FMA8(apA, xA, a0, a1);
        FMA8(apB, xB, a0, a1);
    }
    if (iA < NN) {
        *(float4*)&g_Py[iA * 64 + c0]     = make_float4(apA[0], apA[1], apA[2], apA[3]);
        *(float4*)&g_Py[iA * 64 + c0 + 4] = make_float4(apA[4], apA[5], apA[6], apA[7]);
    }
    if (iB < NN) {
        *(float4*)&g_Py[iB * 64 + c0]     = make_float4(apB[0], apB[1], apB[2], apB[3]);
        *(float4*)&g_Py[iB * 64 + c0 + 4] = make_float4(apB[4], apB[5], apB[6], apB[7]);
    }
    __syncthreads();
    for (int idx = tid; idx < 4096; idx += 256) Ws[idx] = g_B2[idx];
    __syncthreads();
    #pragma unroll
    for (int j = 0; j < 8; j++) { apA[j] = 0.f; apB[j] = 0.f; }
    #pragma unroll 4
    for (int k = 0; k < 64; k++) {
        float xA = buf[k * 65 + el];
        float xB = buf[k * 65 + el + 32];
        float4 a0 = *(const float4*)&Ws[k * 64 + c0];
        float4 a1 = *(const float4*)&Ws[k * 64 + c0 + 4];
        FMA8(apA, xA, a0, a1);
        FMA8(apB, xB, a0, a1);
    }
    if (iA < NN) {
        *(float4*)&g_Qy[iA * 64 + c0]     = make_float4(apA[0], apA[1], apA[2], apA[3]);
        *(float4*)&g_Qy[iA * 64 + c0 + 4] = make_float4(apA[4], apA[5], apA[6], apA[7]);
    }
    if (iB < NN) {
        *(float4*)&g_Qy[iB * 64 + c0]     = make_float4(apB[0], apB[1], apB[2], apB[3]);
        *(float4*)&g_Qy[iB * 64 + c0 + 4] = make_float4(apB[4], apB[5], apB[6], apB[7]);
    }
}

// ---------------- CSR build (single block, side stream) ----------------
__global__ void k_csr(const int* __restrict__ tgt) {
    __shared__ int cnt[1536];
    __shared__ int buf[1536];
    __shared__ int cur[1536];
    int tid = threadIdx.x;                 // 1024 threads
    for (int i = tid; i < 1536; i += 1024) cnt[i] = 0;
    __syncthreads();
    for (int e = tid; e < NEDGE; e += 1024) atomicAdd(&cnt[tgt[e]], 1);
    __syncthreads();
    int* s_ = cnt; int* d_ = buf;
    for (int off = 1; off < 1536; off <<= 1) {
        for (int i = tid; i < 1536; i += 1024)
            d_[i] = s_[i] + ((i >= off) ? s_[i - off] : 0);
        __syncthreads();
        int* tmp = s_; s_ = d_; d_ = tmp;
    }
    if (tid == 0) g_rowptr[0] = 0;
    for (int i = tid; i < NN; i += 1024) g_rowptr[i + 1] = s_[i];
    for (int i = tid; i < 1536; i += 1024) cur[i] = (i == 0) ? 0 : s_[i - 1];
    __syncthreads();
    for (int e = tid; e < NEDGE; e += 1024) {
        int p = atomicAdd(&cur[tgt[e]], 1);
        g_cols[p] = e;
    }
}

// ---------------- output machinery ----------------
__global__ void k_winner_init() {
    int i = blockIdx.x * blockDim.x + threadIdx.x;
    if (i < NN * NN) g_winner[i] = -1;
}

__global__ void k_winner(const int* __restrict__ src, const int* __restrict__ tgt) {
    int e = blockIdx.x * blockDim.x + threadIdx.x;
    if (e < NEDGE) atomicMax(&g_winner[src[e] * NN + tgt[e]], e);
}

__global__ void k_zero(float4* __restrict__ out4) {
    const int total = NN * NN * (EDIM / 4);
    const float4 z = make_float4(0.f, 0.f, 0.f, 0.f);
    for (int idx = blockIdx.x * blockDim.x + threadIdx.x; idx < total;
         idx += gridDim.x * blockDim.x) {
        int row = idx >> 4;
        if (g_winner[row] < 0) out4[idx] = z;
    }
}

__global__ void k_scatter(const int* __restrict__ src, const int* __restrict__ tgt,
                          float* __restrict__ out) {
    int idx = blockIdx.x * blockDim.x + threadIdx.x;
    if (idx < NEDGE * EDIM) {
        int e = idx >> 6, c = idx & 63;
        int s = src[e], t = tgt[e];
        long long slot = (long long)s * NN + t;
        if (g_winner[slot] == e) out[slot * 64 + c] = g_y[idx];
    }
}

__global__ void k_out_x(float* __restrict__ out) {
    int i = blockIdx.x * blockDim.x + threadIdx.x;
    if (i < NN * EDIM) out[(long long)NN * NN * EDIM + i] = g_x[i];
}

// ---------------- launch ----------------
extern "C" void kernel_launch(void* const* d_in, const int* in_sizes, int n_in,
                              void* d_out, int out_size) {
    const float* v      = (const float*)d_in[0];
    const float* labels = (const float*)d_in[1];
    const int*   ei     = (const int*)d_in[4];
    const float* hx_W1 = (const float*)d_in[6],  *hx_b1 = (const float*)d_in[7];
    const float* hx_W2 = (const float*)d_in[8],  *hx_b2 = (const float*)d_in[9];
    const float* hy_W1 = (const float*)d_in[10], *hy_b1 = (const float*)d_in[11];
    const float* hy_W2 = (const float*)d_in[12], *hy_b2 = (const float*)d_in[13];
    const float* fx_W1 = (const float*)d_in[14], *fx_b1 = (const float*)d_in[15];
    const float* fx_W2 = (const float*)d_in[16], *fx_b2 = (const float*)d_in[17];
    const float* fy_W1 = (const float*)d_in[18], *fy_b1 = (const float*)d_in[19];
    const float* fy_W2 = (const float*)d_in[20], *fy_b2 = (const float*)d_in[21];

    const int* src = ei;
    const int* tgt = ei + NEDGE;
    float* out = (float*)d_out;

    static bool attr_done = false;
    if (!attr_done) {
        cudaFuncSetAttribute(k_fx_edge, cudaFuncAttributeMaxDynamicSharedMemorySize,
                             SM_FLOATS * sizeof(float));
        cudaFuncSetAttribute(k_eyA<0>, cudaFuncAttributeMaxDynamicSharedMemorySize,
                             SM_FLOATS * sizeof(float));
        cudaFuncSetAttribute(k_eyA<1>, cudaFuncAttributeMaxDynamicSharedMemorySize,
                             SM_FLOATS * sizeof(float));
        cudaFuncSetAttribute(k_node_B, cudaFuncAttributeMaxDynamicSharedMemorySize,
                             SM_FLOATS * sizeof(float));
        attr_done = true;
    }

    cudaStream_t s2;
    cudaStreamCreateWithFlags(&s2, cudaStreamNonBlocking);
    cudaEvent_t evFork, evCSR, evJoin;
    cudaEventCreateWithFlags(&evFork, cudaEventDisableTiming);
    cudaEventCreateWithFlags(&evCSR, cudaEventDisableTiming);
    cudaEventCreateWithFlags(&evJoin, cudaEventDisableTiming);

    cudaEventRecord(evFork, 0);

    // main pipeline head — k_fx_edge stays at submission index 3 for ncu
    k_prep<<<1, 256>>>(v, labels, fx_W1, fy_W1, hy_W1);                        // #0
    k_init<<<NN, 64>>>(hx_W1, hx_b1, hx_W2, hx_b2);                            // #1
    k_eyA<0><<<EB2 + NT2, 256, SM_FLOATS * sizeof(float)>>>(hy_b1, hy_W2, hy_b2, src, tgt); // #2
    k_fx_edge<<<EB2, 256, SM_FLOATS * sizeof(float)>>>(fx_W1 + 192 * 64, fx_b1, fx_W2, fx_b2, src, tgt); // #3

    // side stream: CSR + winner + zero
    cudaStreamWaitEvent(s2, evFork, 0);
    k_csr<<<1, 1024, 0, s2>>>(tgt);
    cudaEventRecord(evCSR, s2);
    k_winner_init<<<(NN * NN + 255) / 256, 256, 0, s2>>>();
    k_winner<<<(NEDGE + 255) / 256, 256, 0, s2>>>(src, tgt);
    k_zero<<<1184, 512, 0, s2>>>((float4*)out);
    cudaEventRecord(evJoin, s2);

    // loop: fx_edge -> node_B -> ey+nodeA
    cudaStreamWaitEvent(0, evCSR, 0);
    for (int it = 0; it < LOOPN; it++) {
        if (it > 0)
            k_fx_edge<<<EB2, 256, SM_FLOATS * sizeof(float)>>>(fx_W1 + 192 * 64, fx_b1, fx_W2, fx_b2, src, tgt);
        k_node_B<<<NT2, 256, SM_FLOATS * sizeof(float)>>>();
        k_eyA<1><<<EB2 + NT2, 256, SM_FLOATS * sizeof(float)>>>(fy_b1, fy_W2, fy_b2, src, tgt);
    }

    // join side, then outputs
    cudaStreamWaitEvent(0, evJoin, 0);
    k_scatter<<<(NEDGE * EDIM + 255) / 256, 256>>>(src, tgt, out);
    k_out_x<<<(NN * EDIM + 255) / 256, 256>>>(out);
}

// round 12
// speedup vs baseline: 1.1080x; 1.1080x over previous
#include <cuda_runtime.h>
#include <cuda_bf16.h>

#define NN    1500
#define NEDGE 24000
#define EDIM  64
#define LOOPN 10
#define EB2   375            // NEDGE/64 edge tiles (64 edges per block)
#define NT2   24             // ceil(NN/64) node tiles (64 nodes per block)

// ---------------- device scratch (static, allocation-free) ----------------
__device__ float g_vc[NN * 8];
__device__ float g_goal[8];
__device__ float g_x[NN * EDIM];
__device__ float g_y[NEDGE * EDIM];
__device__ float g_msg[NEDGE * EDIM];
__device__ float g_Pf[NN * EDIM], g_Qf[NN * EDIM];
__device__ float g_Py[NN * EDIM], g_Qy[NN * EDIM];
__device__ float g_A1[EDIM * EDIM], g_B1[EDIM * EDIM];
__device__ float g_A2[EDIM * EDIM], g_B2[EDIM * EDIM];
__device__ float g_Ay[8 * EDIM],   g_By[8 * EDIM];
__device__ int   g_rowptr[NN + 1];
__device__ int   g_cols[NEDGE];
__device__ int   g_winner[NN * NN];

#define NEG_INF __int_as_float(0xff800000)

#define FMA8(acc, v, w0, w1)                                   \
    {   acc[0] += (v) * (w0).x; acc[1] += (v) * (w0).y;        \
        acc[2] += (v) * (w0).z; acc[3] += (v) * (w0).w;        \
        acc[4] += (v) * (w1).x; acc[5] += (v) * (w1).y;        \
        acc[6] += (v) * (w1).z; acc[7] += (v) * (w1).w; }

// smem (floats)
#define FX_SM   (4096 + 4096 + 4160 + 4160)   // Wy, W2, ys, hs  = 66 KB
#define EYA_SM  (4096 + 4096 + 4160)          // A,B,xs / W2,hs  = 49.4 KB

// ---------------- prelude ----------------

__global__ void k_prep(const float* __restrict__ v, const float* __restrict__ labels,
                       const float* __restrict__ fxW1, const float* __restrict__ fyW1,
                       const float* __restrict__ hyW1) {
    __shared__ float bv[256];
    __shared__ int   bi[256];
    int t = threadIdx.x;
    for (int i = t; i < NN; i += 256) {
        #pragma unroll
        for (int j = 0; j < 7; j++) g_vc[i * 8 + j] = v[i * 7 + j];
        g_vc[i * 8 + 7] = labels[i];
    }
    float best = -1e30f; int idx = 0;
    for (int i = t; i < NN; i += 256) {
        float l = labels[i];
        if (l > best) { best = l; idx = i; }
    }
    bv[t] = best; bi[t] = idx;
    __syncthreads();
    for (int s = 128; s > 0; s >>= 1) {
        if (t < s) {
            if (bv[t + s] > bv[t] || (bv[t + s] == bv[t] && bi[t + s] < bi[t])) {
                bv[t] = bv[t + s]; bi[t] = bi[t + s];
            }
        }
        __syncthreads();
    }
    if (t < 8) g_goal[t] = g_vc[bi[0] * 8 + t];
    for (int i = t; i < 4096; i += 256) {
        g_A1[i] = fxW1[i] + fxW1[4096 + i];
        g_B1[i] = fxW1[8192 + i] - fxW1[i];
        g_A2[i] = fyW1[i] + fyW1[4096 + i];
        g_B2[i] = fyW1[8192 + i] - fyW1[i];
        if (i < 512) {
            g_Ay[i] = hyW1[i] + hyW1[512 + i];
            g_By[i] = hyW1[1024 + i] - hyW1[i];
        }
    }
}

__global__ void k_init(const float* __restrict__ W1, const float* __restrict__ b1,
                       const float* __restrict__ W2, const float* __restrict__ b2) {
    int i = blockIdx.x;
    int c = threadIdx.x;                 // 64 threads
    __shared__ float z[32], h[64];
    if (c < 8) {
        float vcv = g_vc[i * 8 + c];
        float gl  = g_goal[c];
        float d   = vcv - gl;
        z[c] = vcv; z[8 + c] = gl; z[16 + c] = d; z[24 + c] = d * d;
    }
    __syncthreads();
    float acc = b1[c];
    #pragma unroll
    for (int k = 0; k < 32; k++) acc += z[k] * W1[k * 64 + c];
    h[c] = fmaxf(acc, 0.0f);
    __syncthreads();
    float o = b2[c];
    #pragma unroll 16
    for (int k = 0; k < 64; k++) o += h[k] * W2[k * 64 + c];
    g_x[i * 64 + c] = o;
    float r = 0.f, s = 0.f;
    #pragma unroll
    for (int k = 0; k < 8; k++) {
        r += z[k] * g_Ay[k * 64 + c];
        s += z[k] * g_By[k * 64 + c];
    }
    g_Py[i * 64 + c] = r;
    g_Qy[i * 64 + c] = s;
}

// ---------------- fx edge kernel: 64 edges/block, 512 threads, split-k ----------------
__global__ void __launch_bounds__(512, 3)
k_fx_edge(const float* __restrict__ Wy, const float* __restrict__ b1,
          const float* __restrict__ W2, const float* __restrict__ b2,
          const int* __restrict__ src, const int* __restrict__ tgt) {
    extern __shared__ float sm[];
    float* Wys = sm;
    float* W2s = sm + 4096;
    float* ys  = sm + 8192;
    float* hs  = sm + 12352;
    int tid = threadIdx.x;
    int e0  = blockIdx.x * 64;
    for (int idx = tid; idx < 4096; idx += 512) {
        Wys[idx] = Wy[idx];
        W2s[idx] = W2[idx];
        int el2 = idx >> 6, k = idx & 63;
        ys[k * 65 + el2] = g_y[(e0 + el2) * 64 + k];
    }
    __syncthreads();
    int lane = tid & 31;
    int o  = ((tid >> 5) << 4) | (lane & 15);   // 0..255 output id
    int el = o >> 3;                            // 0..31
    int c0 = (o & 7) << 3;
    int kh = lane >> 4;                         // 0/1: even/odd k
    int eA = e0 + el, eB = eA + 32;

    float accA[8], accB[8];
    #pragma unroll
    for (int j = 0; j < 8; j++) { accA[j] = 0.f; accB[j] = 0.f; }
    #pragma unroll 4
    for (int kk = 0; kk < 32; kk++) {
        int k = (kk << 1) | kh;
        float yA = ys[k * 65 + el];
        float yB = ys[k * 65 + el + 32];
        float4 w0 = *(const float4*)&Wys[k * 64 + c0];
        float4 w1 = *(const float4*)&Wys[k * 64 + c0 + 4];
        FMA8(accA, yA, w0, w1);
        FMA8(accB, yB, w0, w1);
    }
    #pragma unroll
    for (int j = 0; j < 8; j++) {
        accA[j] += __shfl_xor_sync(0xffffffffu, accA[j], 16);
        accB[j] += __shfl_xor_sync(0xffffffffu, accB[j], 16);
    }
    if (kh == 0) {
        int sA = src[eA], tA = tgt[eA];
        int sB = src[eB], tB = tgt[eB];
        float4 pA0 = *(const float4*)&g_Pf[sA * 64 + c0];
        float4 pA1 = *(const float4*)&g_Pf[sA * 64 + c0 + 4];
        float4 qA0 = *(const float4*)&g_Qf[tA * 64 + c0];
        float4 qA1 = *(const float4*)&g_Qf[tA * 64 + c0 + 4];
        float4 pB0 = *(const float4*)&g_Pf[sB * 64 + c0];
        float4 pB1 = *(const float4*)&g_Pf[sB * 64 + c0 + 4];
        float4 qB0 = *(const float4*)&g_Qf[tB * 64 + c0];
        float4 qB1 = *(const float4*)&g_Qf[tB * 64 + c0 + 4];
        hs[(c0 + 0) * 65 + el] = fmaxf(accA[0] + pA0.x + qA0.x + b1[c0 + 0], 0.f);
        hs[(c0 + 1) * 65 + el] = fmaxf(accA[1] + pA0.y + qA0.y + b1[c0 + 1], 0.f);
        hs[(c0 + 2) * 65 + el] = fmaxf(accA[2] + pA0.z + qA0.z + b1[c0 + 2], 0.f);
        hs[(c0 + 3) * 65 + el] = fmaxf(accA[3] + pA0.w + qA0.w + b1[c0 + 3], 0.f);
        hs[(c0 + 4) * 65 + el] = fmaxf(accA[4] + pA1.x + qA1.x + b1[c0 + 4], 0.f);
        hs[(c0 + 5) * 65 + el] = fmaxf(accA[5] + pA1.y + qA1.y + b1[c0 + 5], 0.f);
        hs[(c0 + 6) * 65 + el] = fmaxf(accA[6] + pA1.z + qA1.z + b1[c0 + 6], 0.f);
        hs[(c0 + 7) * 65 + el] = fmaxf(accA[7] + pA1.w + qA1.w + b1[c0 + 7], 0.f);
        hs[(c0 + 0) * 65 + el + 32] = fmaxf(accB[0] + pB0.x + qB0.x + b1[c0 + 0], 0.f);
        hs[(c0 + 1) * 65 + el + 32] = fmaxf(accB[1] + pB0.y + qB0.y + b1[c0 + 1], 0.f);
        hs[(c0 + 2) * 65 + el + 32] = fmaxf(accB[2] + pB0.z + qB0.z + b1[c0 + 2], 0.f);
        hs[(c0 + 3) * 65 + el + 32] = fmaxf(accB[3] + pB0.w + qB0.w + b1[c0 + 3], 0.f);
        hs[(c0 + 4) * 65 + el + 32] = fmaxf(accB[4] + pB1.x + qB1.x + b1[c0 + 4], 0.f);
        hs[(c0 + 5) * 65 + el + 32] = fmaxf(accB[5] + pB1.y + qB1.y + b1[c0 + 5], 0.f);
        hs[(c0 + 6) * 65 + el + 32] = fmaxf(accB[6] + pB1.z + qB1.z + b1[c0 + 6], 0.f);
        hs[(c0 + 7) * 65 + el + 32] = fmaxf(accB[7] + pB1.w + qB1.w + b1[c0 + 7], 0.f);
    }
    __syncthreads();
    #pragma unroll
    for (int j = 0; j < 8; j++) { accA[j] = 0.f; accB[j] = 0.f; }
    #pragma unroll 4
    for (int kk = 0; kk < 32; kk++) {
        int k = (kk << 1) | kh;
        float hA = hs[k * 65 + el];
        float hB = hs[k * 65 + el + 32];
        float4 w0 = *(const float4*)&W2s[k * 64 + c0];
        float4 w1 = *(const float4*)&W2s[k * 64 + c0 + 4];
        FMA8(accA, hA, w0, w1);
        FMA8(accB, hB, w0, w1);
    }
    #pragma unroll
    for (int j = 0; j < 8; j++) {
        accA[j] += __shfl_xor_sync(0xffffffffu, accA[j], 16);
        accB[j] += __shfl_xor_sync(0xffffffffu, accB[j], 16);
    }
    if (kh == 0) {
        #pragma unroll
        for (int j = 0; j < 8; j++) { accA[j] += b2[c0 + j]; accB[j] += b2[c0 + j]; }
        *(float4*)&g_msg[eA * 64 + c0]     = make_float4(accA[0], accA[1], accA[2], accA[3]);
        *(float4*)&g_msg[eA * 64 + c0 + 4] = make_float4(accA[4], accA[5], accA[6], accA[7]);
        *(float4*)&g_msg[eB * 64 + c0]     = make_float4(accB[0], accB[1], accB[2], accB[3]);
        *(float4*)&g_msg[eB * 64 + c0 + 4] = make_float4(accB[4], accB[5], accB[6], accB[7]);
    }
}

// ---------------- fused edge-y + node_A: 512 threads ----------------
template <int MODE>
__global__ void __launch_bounds__(512, 3)
k_eyA(const float* __restrict__ b1, const float* __restrict__ W2,
      const float* __restrict__ b2,
      const int* __restrict__ src, const int* __restrict__ tgt) {
    extern __shared__ float sm[];
    int tid = threadIdx.x;

    if (blockIdx.x < EB2) {
        // ---- edge y-MLP (64 edges), split-k GEMM ----
        float* Ws = sm;
        float* hs = sm + 4096;
        int e0 = blockIdx.x * 64;
        for (int idx = tid; idx < 4096; idx += 512) Ws[idx] = W2[idx];
        // h: each thread 1 edge x 8 cols
        {
            int nl = tid >> 3, cc = (tid & 7) << 3;
            int e = e0 + nl;
            int s = src[e], t = tgt[e];
            float4 p0 = *(const float4*)&g_Py[t * 64 + cc];
            float4 p1 = *(const float4*)&g_Py[t * 64 + cc + 4];
            float4 q0 = *(const float4*)&g_Qy[s * 64 + cc];
            float4 q1 = *(const float4*)&g_Qy[s * 64 + cc + 4];
            hs[(cc + 0) * 65 + nl] = fmaxf(p0.x + q0.x + b1[cc + 0], 0.f);
            hs[(cc + 1) * 65 + nl] = fmaxf(p0.y + q0.y + b1[cc + 1], 0.f);
            hs[(cc + 2) * 65 + nl] = fmaxf(p0.z + q0.z + b1[cc + 2], 0.f);
            hs[(cc + 3) * 65 + nl] = fmaxf(p0.w + q0.w + b1[cc + 3], 0.f);
            hs[(cc + 4) * 65 + nl] = fmaxf(p1.x + q1.x + b1[cc + 4], 0.f);
            hs[(cc + 5) * 65 + nl] = fmaxf(p1.y + q1.y + b1[cc + 5], 0.f);
            hs[(cc + 6) * 65 + nl] = fmaxf(p1.z + q1.z + b1[cc + 6], 0.f);
            hs[(cc + 7) * 65 + nl] = fmaxf(p1.w + q1.w + b1[cc + 7], 0.f);
        }
        __syncthreads();
        int lane = tid & 31;
        int o  = ((tid >> 5) << 4) | (lane & 15);
        int el = o >> 3, c0 = (o & 7) << 3;
        int kh = lane >> 4;
        int eA = e0 + el, eB = eA + 32;
        float accA[8], accB[8];
        #pragma unroll
        for (int j = 0; j < 8; j++) { accA[j] = 0.f; accB[j] = 0.f; }
        #pragma unroll 4
        for (int kk = 0; kk < 32; kk++) {
            int k = (kk << 1) | kh;
            float hA = hs[k * 65 + el];
            float hB = hs[k * 65 + el + 32];
            float4 w0 = *(const float4*)&Ws[k * 64 + c0];
            float4 w1 = *(const float4*)&Ws[k * 64 + c0 + 4];
            FMA8(accA, hA, w0, w1);
            FMA8(accB, hB, w0, w1);
        }
        #pragma unroll
        for (int j = 0; j < 8; j++) {
            accA[j] += __shfl_xor_sync(0xffffffffu, accA[j], 16);
            accB[j] += __shfl_xor_sync(0xffffffffu, accB[j], 16);
        }
        if (kh == 0) {
            #pragma unroll
            for (int j = 0; j < 8; j++) { accA[j] += b2[c0 + j]; accB[j] += b2[c0 + j]; }
            if (MODE == 0) {
                *(float4*)&g_y[eA * 64 + c0]     = make_float4(accA[0], accA[1], accA[2], accA[3]);
                *(float4*)&g_y[eA * 64 + c0 + 4] = make_float4(accA[4], accA[5], accA[6], accA[7]);
                *(float4*)&g_y[eB * 64 + c0]     = make_float4(accB[0], accB[1], accB[2], accB[3]);
                *(float4*)&g_y[eB * 64 + c0 + 4] = make_float4(accB[4], accB[5], accB[6], accB[7]);
            } else {
                float4 ya0 = *(const float4*)&g_y[eA * 64 + c0];
                float4 ya1 = *(const float4*)&g_y[eA * 64 + c0 + 4];
                float4 yb0 = *(const float4*)&g_y[eB * 64 + c0];
                float4 yb1 = *(const float4*)&g_y[eB * 64 + c0 + 4];
                *(float4*)&g_y[eA * 64 + c0] = make_float4(
                    fmaxf(ya0.x, accA[0]), fmaxf(ya0.y, accA[1]),
                    fmaxf(ya0.z, accA[2]), fmaxf(ya0.w, accA[3]));
                *(float4*)&g_y[eA * 64 + c0 + 4] = make_float4(
                    fmaxf(ya1.x, accA[4]), fmaxf(ya1.y, accA[5]),
                    fmaxf(ya1.z, accA[6]), fmaxf(ya1.w, accA[7]));
                *(float4*)&g_y[eB * 64 + c0] = make_float4(
                    fmaxf(yb0.x, accB[0]), fmaxf(yb0.y, accB[1]),
                    fmaxf(yb0.z, accB[2]), fmaxf(yb0.w, accB[3]));
                *(float4*)&g_y[eB * 64 + c0 + 4] = make_float4(
                    fmaxf(yb1.x, accB[4]), fmaxf(yb1.y, accB[5]),
                    fmaxf(yb1.z, accB[6]), fmaxf(yb1.w, accB[7]));
            }
        }
    } else {
        // ---- node_A: group 0 -> Pf = x@A1, group 1 -> Qf = x@B1 ----
        float* Wa = sm;
        float* Wb = sm + 4096;
        float* xs = sm + 8192;
        int i0 = (blockIdx.x - EB2) * 64;
        for (int idx = tid; idx < 4096; idx += 512) {
            Wa[idx] = g_A1[idx];
            Wb[idx] = g_B1[idx];
            int nl2 = idx >> 6, k = idx & 63, i = i0 + nl2;
            xs[k * 65 + nl2] = (i < NN) ? g_x[i * 64 + k] : 0.f;
        }
        __syncthreads();
        int g  = tid >> 8;               // 0: A-matrix, 1: B-matrix
        int t2 = tid & 255;
        int el = t2 >> 3, c0 = (t2 & 7) << 3;
        const float* W = g ? Wb : Wa;
        float aA[8], aB[8];
        #pragma unroll
        for (int j = 0; j < 8; j++) { aA[j] = 0.f; aB[j] = 0.f; }
        #pragma unroll 4
        for (int k = 0; k < 64; k++) {
            float xA = xs[k * 65 + el];
            float xB = xs[k * 65 + el + 32];
            float4 w0 = *(const float4*)&W[k * 64 + c0];
            float4 w1 = *(const float4*)&W[k * 64 + c0 + 4];
            FMA8(aA, xA, w0, w1);
            FMA8(aB, xB, w0, w1);
        }
        float* O = g ? g_Qf : g_Pf;
        int iA = i0 + el, iB = iA + 32;
        if (iA < NN) {
            *(float4*)&O[iA * 64 + c0]     = make_float4(aA[0], aA[1], aA[2], aA[3]);
            *(float4*)&O[iA * 64 + c0 + 4] = make_float4(aA[4], aA[5], aA[6], aA[7]);
        }
        if (iB < NN) {
            *(float4*)&O[iB * 64 + c0]     = make_float4(aB[0], aB[1], aB[2], aB[3]);
            *(float4*)&O[iB * 64 + c0 + 4] = make_float4(aB[4], aB[5], aB[6], aB[7]);
        }
    }
}

// ---------------- node_B: CSR gather-max + x update + split A2/B2 GEMMs ----------------
__global__ void __launch_bounds__(512, 3)
k_node_B() {
    extern __shared__ float sm[];
    float* Wa = sm;
    float* Wb = sm + 4096;
    float* xs = sm + 8192;
    int tid = threadIdx.x;
    int i0  = blockIdx.x * 64;
    for (int idx = tid; idx < 4096; idx += 512) {
        Wa[idx] = g_A2[idx];
        Wb[idx] = g_B2[idx];
    }
    // gather-max: each thread one node x 8 cols
    {
        int nl = tid >> 3, cc = (tid & 7) << 3;
        int i = i0 + nl;
        if (i < NN) {
            float m[8];
            #pragma unroll
            for (int j = 0; j < 8; j++) m[j] = NEG_INF;
            int p0 = g_rowptr[i], p1 = g_rowptr[i + 1];
            for (int p = p0; p < p1; p++) {
                int e = g_cols[p];
                float4 a = *(const float4*)&g_msg[e * 64 + cc];
                float4 b = *(const float4*)&g_msg[e * 64 + cc + 4];
                m[0] = fmaxf(m[0], a.x); m[1] = fmaxf(m[1], a.y);
                m[2] = fmaxf(m[2], a.z); m[3] = fmaxf(m[3], a.w);
                m[4] = fmaxf(m[4], b.x); m[5] = fmaxf(m[5], b.y);
                m[6] = fmaxf(m[6], b.z); m[7] = fmaxf(m[7], b.w);
            }
            if (p1 == p0) {
                #pragma unroll
                for (int j = 0; j < 8; j++) m[j] = 0.f;
            }
            #pragma unroll
            for (int j = 0; j < 8; j++) {
                float xn = fmaxf(g_x[i * 64 + cc + j], m[j]);
                g_x[i * 64 + cc + j] = xn;
                xs[(cc + j) * 65 + nl] = xn;
            }
        } else {
            #pragma unroll
            for (int j = 0; j < 8; j++) xs[(cc + j) * 65 + nl] = 0.f;
        }
    }
    __syncthreads();
    int g  = tid >> 8;
    int t2 = tid & 255;
    int el = t2 >> 3, c0 = (t2 & 7) << 3;
    const float* W = g ? Wb : Wa;
    float aA[8], aB[8];
    #pragma unroll
    for (int j = 0; j < 8; j++) { aA[j] = 0.f; aB[j] = 0.f; }
    #pragma unroll 4
    for (int k = 0; k < 64; k++) {
        float xA = xs[k * 65 + el];
        float xB = xs[k * 65 + el + 32];
        float4 w0 = *(const float4*)&W[k * 64 + c0];
        float4 w1 = *(const float4*)&W[k * 64 + c0 + 4];
        FMA8(aA, xA, w0, w1);
        FMA8(aB, xB, w0, w1);
    }
    float* O = g ? g_Qy : g_Py;
    int iA = i0 + el, iB = iA + 32;
    if (iA < NN) {
        *(float4*)&O[iA * 64 + c0]     = make_float4(aA[0], aA[1], aA[2], aA[3]);
        *(float4*)&O[iA * 64 + c0 + 4] = make_float4(aA[4], aA[5], aA[6], aA[7]);
    }
    if (iB < NN) {
        *(float4*)&O[iB * 64 + c0]     = make_float4(aB[0], aB[1], aB[2], aB[3]);
        *(float4*)&O[iB * 64 + c0 + 4] = make_float4(aB[4], aB[5], aB[6], aB[7]);
    }
}

// ---------------- CSR build (single block, side stream) ----------------
__global__ void k_csr(const int* __restrict__ tgt) {
    __shared__ int cnt[1536];
    __shared__ int buf[1536];
    __shared__ int cur[1536];
    int tid = threadIdx.x;                 // 1024 threads
    for (int i = tid; i < 1536; i += 1024) cnt[i] = 0;
    __syncthreads();
    for (int e = tid; e < NEDGE; e += 1024) atomicAdd(&cnt[tgt[e]], 1);
    __syncthreads();
    int* s_ = cnt; int* d_ = buf;
    for (int off = 1; off < 1536; off <<= 1) {
        for (int i = tid; i < 1536; i += 1024)
            d_[i] = s_[i] + ((i >= off) ? s_[i - off] : 0);
        __syncthreads();
        int* tmp = s_; s_ = d_; d_ = tmp;
    }
    if (tid == 0) g_rowptr[0] = 0;
    for (int i = tid; i < NN; i += 1024) g_rowptr[i + 1] = s_[i];
    for (int i = tid; i < 1536; i += 1024) cur[i] = (i == 0) ? 0 : s_[i - 1];
    __syncthreads();
    for (int e = tid; e < NEDGE; e += 1024) {
        int p = atomicAdd(&cur[tgt[e]], 1);
        g_cols[p] = e;
    }
}

// ---------------- output machinery ----------------
__global__ void k_winner_init() {
    int i = blockIdx.x * blockDim.x + threadIdx.x;
    if (i < NN * NN) g_winner[i] = -1;
}

__global__ void k_winner(const int* __restrict__ src, const int* __restrict__ tgt) {
    int e = blockIdx.x * blockDim.x + threadIdx.x;
    if (e < NEDGE) atomicMax(&g_winner[src[e] * NN + tgt[e]], e);
}

__global__ void k_zero(float4* __restrict__ out4) {
    const int total = NN * NN * (EDIM / 4);
    const float4 z = make_float4(0.f, 0.f, 0.f, 0.f);
    for (int idx = blockIdx.x * blockDim.x + threadIdx.x; idx < total;
         idx += gridDim.x * blockDim.x) {
        int row = idx >> 4;
        if (g_winner[row] < 0) out4[idx] = z;
    }
}

__global__ void k_scatter(const int* __restrict__ src, const int* __restrict__ tgt,
                          float* __restrict__ out) {
    int idx = blockIdx.x * blockDim.x + threadIdx.x;
    if (idx < NEDGE * EDIM) {
        int e = idx >> 6, c = idx & 63;
        int s = src[e], t = tgt[e];
        long long slot = (long long)s * NN + t;
        if (g_winner[slot] == e) out[slot * 64 + c] = g_y[idx];
    }
}

__global__ void k_out_x(float* __restrict__ out) {
    int i = blockIdx.x * blockDim.x + threadIdx.x;
    if (i < NN * EDIM) out[(long long)NN * NN * EDIM + i] = g_x[i];
}

// ---------------- launch ----------------
extern "C" void kernel_launch(void* const* d_in, const int* in_sizes, int n_in,
                              void* d_out, int out_size) {
    const float* v      = (const float*)d_in[0];
    const float* labels = (const float*)d_in[1];
    const int*   ei     = (const int*)d_in[4];
    const float* hx_W1 = (const float*)d_in[6],  *hx_b1 = (const float*)d_in[7];
    const float* hx_W2 = (const float*)d_in[8],  *hx_b2 = (const float*)d_in[9];
    const float* hy_W1 = (const float*)d_in[10], *hy_b1 = (const float*)d_in[11];
    const float* hy_W2 = (const float*)d_in[12], *hy_b2 = (const float*)d_in[13];
    const float* fx_W1 = (const float*)d_in[14], *fx_b1 = (const float*)d_in[15];
    const float* fx_W2 = (const float*)d_in[16], *fx_b2 = (const float*)d_in[17];
    const float* fy_W1 = (const float*)d_in[18], *fy_b1 = (const float*)d_in[19];
    const float* fy_W2 = (const float*)d_in[20], *fy_b2 = (const float*)d_in[21];

    const int* src = ei;
    const int* tgt = ei + NEDGE;
    float* out = (float*)d_out;

    static bool attr_done = false;
    if (!attr_done) {
        cudaFuncSetAttribute(k_fx_edge, cudaFuncAttributeMaxDynamicSharedMemorySize,
                             FX_SM * sizeof(float));
        cudaFuncSetAttribute(k_eyA<0>, cudaFuncAttributeMaxDynamicSharedMemorySize,
                             EYA_SM * sizeof(float));
        cudaFuncSetAttribute(k_eyA<1>, cudaFuncAttributeMaxDynamicSharedMemorySize,
                             EYA_SM * sizeof(float));
        cudaFuncSetAttribute(k_node_B, cudaFuncAttributeMaxDynamicSharedMemorySize,
                             EYA_SM * sizeof(float));
        attr_done = true;
    }

    cudaStream_t s2;
    cudaStreamCreateWithFlags(&s2, cudaStreamNonBlocking);
    cudaEvent_t evFork, evCSR, evJoin;
    cudaEventCreateWithFlags(&evFork, cudaEventDisableTiming);
    cudaEventCreateWithFlags(&evCSR, cudaEventDisableTiming);
    cudaEventCreateWithFlags(&evJoin, cudaEventDisableTiming);

    cudaEventRecord(evFork, 0);

    // main pipeline head — k_fx_edge stays at submission index 3 for ncu
    k_prep<<<1, 256>>>(v, labels, fx_W1, fy_W1, hy_W1);                        // #0
    k_init<<<NN, 64>>>(hx_W1, hx_b1, hx_W2, hx_b2);                            // #1
    k_eyA<0><<<EB2 + NT2, 512, EYA_SM * sizeof(float)>>>(hy_b1, hy_W2, hy_b2, src, tgt); // #2
    k_fx_edge<<<EB2, 512, FX_SM * sizeof(float)>>>(fx_W1 + 192 * 64, fx_b1, fx_W2, fx_b2, src, tgt); // #3

    // side stream: CSR + winner + zero
    cudaStreamWaitEvent(s2, evFork, 0);
    k_csr<<<1, 1024, 0, s2>>>(tgt);
    cudaEventRecord(evCSR, s2);
    k_winner_init<<<(NN * NN + 255) / 256, 256, 0, s2>>>();
    k_winner<<<(NEDGE + 255) / 256, 256, 0, s2>>>(src, tgt);
    k_zero<<<1184, 512, 0, s2>>>((float4*)out);
    cudaEventRecord(evJoin, s2);

    // loop: fx_edge -> node_B -> ey+nodeA
    cudaStreamWaitEvent(0, evCSR, 0);
    for (int it = 0; it < LOOPN; it++) {
        if (it > 0)
            k_fx_edge<<<EB2, 512, FX_SM * sizeof(float)>>>(fx_W1 + 192 * 64, fx_b1, fx_W2, fx_b2, src, tgt);
        k_node_B<<<NT2, 512, EYA_SM * sizeof(float)>>>();
        k_eyA<1><<<EB2 + NT2, 512, EYA_SM * sizeof(float)>>>(fy_b1, fy_W2, fy_b2, src, tgt);
    }

    // join side, then outputs
    cudaStreamWaitEvent(0, evJoin, 0);
    k_scatter<<<(NEDGE * EDIM + 255) / 256, 256>>>(src, tgt, out);
    k_out_x<<<(NN * EDIM + 255) / 256, 256>>>(out);
}